// round 14
// baseline (speedup 1.0000x reference)
#include <cuda_runtime.h>
#include <cuda_bf16.h>
#include <cstdint>
#include <math.h>

// ---------------- problem constants ----------------
#define T_TOKENS 2048
#define D_MODEL  2048
#define F_INTER  1408
#define FS_INTER 2816
#define N_EXP    32
#define TOPK     6
#define CAP      768              // 2 * (2048*6/32)
#define NASSIGN  (T_TOKENS*TOPK)  // 12288

// ---------------- GEMM tiling ----------------
#define BM 128
#define BN 64
#define BK 32
#define XS_STRIDE 40   // bf16 elems per A-tile smem row (80B, ldmatrix conflict-free)
#define WS_STRIDE 72   // bf16 elems per B-tile smem row (144B, conflict-free)

// ---------------- device scratch (no cudaMalloc allowed) ----------------
__device__ int   g_topk_idx[NASSIGN];
__device__ float g_topk_w[NASSIGN];
__device__ int   g_pos[NASSIGN];
__device__ int   g_rows[N_EXP*CAP];
__device__ int   g_count[N_EXP];
__device__ float g_H [(size_t)N_EXP*CAP*F_INTER];     // expert hidden  (~138 MB)
__device__ float g_Hs[(size_t)T_TOKENS*FS_INTER];     // shared hidden  (~23 MB)
__device__ float g_Y [(size_t)NASSIGN*D_MODEL];       // per-assignment down output (~100 MB)

// ---------------- helpers ----------------
__device__ __forceinline__ uint32_t smem_u32(const void* p){
    return (uint32_t)__cvta_generic_to_shared(p);
}
__device__ __forceinline__ void bf16_split(float v, __nv_bfloat16& h, __nv_bfloat16& l){
    h = __float2bfloat16(v);
    l = __float2bfloat16(v - __bfloat162float(h));
}
__device__ __forceinline__ void ldsm4(uint32_t &r0,uint32_t &r1,uint32_t &r2,uint32_t &r3, uint32_t addr){
    asm volatile("ldmatrix.sync.aligned.m8n8.x4.shared.b16 {%0,%1,%2,%3},[%4];\n"
                 :"=r"(r0),"=r"(r1),"=r"(r2),"=r"(r3):"r"(addr));
}
__device__ __forceinline__ void ldsm4t(uint32_t &r0,uint32_t &r1,uint32_t &r2,uint32_t &r3, uint32_t addr){
    asm volatile("ldmatrix.sync.aligned.m8n8.x4.trans.shared.b16 {%0,%1,%2,%3},[%4];\n"
                 :"=r"(r0),"=r"(r1),"=r"(r2),"=r"(r3):"r"(addr));
}
__device__ __forceinline__ void mma16816(float* c,
        uint32_t a0,uint32_t a1,uint32_t a2,uint32_t a3, uint32_t b0,uint32_t b1){
    asm volatile("mma.sync.aligned.m16n8k16.row.col.f32.bf16.bf16.f32 "
                 "{%0,%1,%2,%3},{%4,%5,%6,%7},{%8,%9},{%0,%1,%2,%3};\n"
                 :"+f"(c[0]),"+f"(c[1]),"+f"(c[2]),"+f"(c[3])
                 :"r"(a0),"r"(a1),"r"(a2),"r"(a3),"r"(b0),"r"(b1));
}

// ================= router: softmax + top-6 =================
__global__ void router_kernel(const float* __restrict__ x, const float* __restrict__ wg)
{
    const int t = blockIdx.x;
    const int tid = threadIdx.x;               // 128 threads
    const int warp = tid >> 5, lane = tid & 31;
    __shared__ float s_sc[N_EXP];
    const float* xr = x + (size_t)t * D_MODEL;
    for (int e = warp; e < N_EXP; e += 4){
        const float* w = wg + (size_t)e * D_MODEL;
        float acc = 0.f;
        for (int d = lane * 4; d < D_MODEL; d += 128){
            float4 xv = *(const float4*)(xr + d);
            float4 wv = *(const float4*)(w + d);
            acc += xv.x*wv.x + xv.y*wv.y + xv.z*wv.z + xv.w*wv.w;
        }
        #pragma unroll
        for (int o = 16; o; o >>= 1) acc += __shfl_xor_sync(0xffffffffu, acc, o);
        if (lane == 0) s_sc[e] = acc;
    }
    __syncthreads();
    if (warp == 0){
        float v = s_sc[lane];
        float m = v;
        #pragma unroll
        for (int o = 16; o; o >>= 1) m = fmaxf(m, __shfl_xor_sync(0xffffffffu, m, o));
        float ev = expf(v - m);
        float Z = ev;
        #pragma unroll
        for (int o = 16; o; o >>= 1) Z += __shfl_xor_sync(0xffffffffu, Z, o);
        float s = ev / Z;          // softmax score for expert = lane
        float cur = s;
        float sum6 = 0.f;
        int   sel_idx = 0; float sel_val = 0.f;
        #pragma unroll
        for (int k = 0; k < TOPK; k++){
            float bv = cur; int bi = lane;
            #pragma unroll
            for (int o = 16; o; o >>= 1){
                float ovv = __shfl_xor_sync(0xffffffffu, bv, o);
                int   oi  = __shfl_xor_sync(0xffffffffu, bi, o);
                if (ovv > bv || (ovv == bv && oi < bi)){ bv = ovv; bi = oi; }
            }
            sum6 += bv;
            if (lane == k){ sel_idx = bi; sel_val = bv; }
            if (lane == bi) cur = -1.f;   // scores in (0,1): -1 acts as -inf
        }
        if (lane < TOPK){
            g_topk_idx[t*TOPK + lane] = sel_idx;
            g_topk_w [t*TOPK + lane] = sel_val / (sum6 + 1e-20f);
        }
    }
}

// ======= dispatch: flattened-order positions (matches jnp.cumsum order) =======
__global__ void dispatch_kernel()
{
    __shared__ int s_idx[NASSIGN];   // 48 KB
    for (int i = threadIdx.x; i < NASSIGN; i += 1024) s_idx[i] = g_topk_idx[i];
    __syncthreads();
    const int warp = threadIdx.x >> 5;   // expert id (32 warps)
    const int lane = threadIdx.x & 31;
    int count = 0;
    for (int base = 0; base < NASSIGN; base += 32){
        int eidx = s_idx[base + lane];
        unsigned msk = __ballot_sync(0xffffffffu, eidx == warp);
        if (eidx == warp){
            int p = count + __popc(msk & ((1u << lane) - 1u));
            g_pos[base + lane] = p;
            if (p < CAP) g_rows[warp*CAP + p] = base + lane;
        }
        count += __popc(msk);
    }
    if (lane == 0) g_count[warp] = (count < CAP) ? count : CAP;
}

// ======= fused gate/up SwiGLU grouped GEMM (bf16 3-term split, fp32 accum) =======
template<bool GATHER>
__global__ __launch_bounds__(256, 2)
void gateup_kernel(const float* __restrict__ x,
                   const float* __restrict__ Wg,
                   const float* __restrict__ Wu,
                   int N, int Mtot)
{
    __shared__ __align__(16) __nv_bfloat16 sXh[BM][XS_STRIDE];
    __shared__ __align__(16) __nv_bfloat16 sXl[BM][XS_STRIDE];
    __shared__ __align__(16) __nv_bfloat16 sWh[2][BK][WS_STRIDE];   // [0]=gate [1]=up
    __shared__ __align__(16) __nv_bfloat16 sWl[2][BK][WS_STRIDE];
    __shared__ int s_tok[BM];

    const int e = blockIdx.z;
    const int rows = GATHER ? g_count[e] : Mtot;
    const int m0 = blockIdx.y * BM;
    if (m0 >= rows) return;
    const int n0 = blockIdx.x * BN;
    const int tid = threadIdx.x;
    const int lane = tid & 31, warp = tid >> 5;
    const int wm = warp & 3, wn = warp >> 2;

    const float* wgp = GATHER ? (Wg + (size_t)e * D_MODEL * N) : Wg;
    const float* wup = GATHER ? (Wu + (size_t)e * D_MODEL * N) : Wu;
    float* hout      = GATHER ? (g_H + (size_t)e * CAP * N)    : g_Hs;

    if (tid < BM){
        int r = m0 + tid;
        int tok = -1;
        if (r < rows) tok = GATHER ? (g_rows[e*CAP + r] / TOPK) : r;
        s_tok[tid] = tok;
    }
    __syncthreads();

    float accG[2][4][4], accU[2][4][4];
    #pragma unroll
    for (int a = 0; a < 2; a++)
        #pragma unroll
        for (int b = 0; b < 4; b++)
            #pragma unroll
            for (int c = 0; c < 4; c++){ accG[a][b][c] = 0.f; accU[a][b][c] = 0.f; }

    const int aRow  = wm*32 + (lane & 15);
    const int aColB = 8 * (lane >> 4);
    const uint32_t aBaseH = smem_u32(&sXh[aRow][aColB]);
    const uint32_t aBaseL = smem_u32(&sXl[aRow][aColB]);
    const int bRow  = (lane & 15);
    const int bColB = wn*32 + 8*(lane >> 4);
    const uint32_t bgBaseH = smem_u32(&sWh[0][bRow][bColB]);
    const uint32_t bgBaseL = smem_u32(&sWl[0][bRow][bColB]);
    const uint32_t buBaseH = smem_u32(&sWh[1][bRow][bColB]);
    const uint32_t buBaseL = smem_u32(&sWl[1][bRow][bColB]);

    for (int k0 = 0; k0 < D_MODEL; k0 += BK){
        // ---- stage X tile (gathered rows), split to hi/lo bf16 ----
        {
            const int row = tid >> 1;
            const int cb  = (tid & 1) * 16;
            const int tok = s_tok[row];
            if (tok >= 0){
                const float* p = x + (size_t)tok * D_MODEL + k0 + cb;
                #pragma unroll
                for (int i = 0; i < 16; i += 4){
                    float4 v = *(const float4*)(p + i);
                    float vv[4] = {v.x, v.y, v.z, v.w};
                    #pragma unroll
                    for (int j = 0; j < 4; j++){
                        __nv_bfloat16 h, l; bf16_split(vv[j], h, l);
                        sXh[row][cb+i+j] = h; sXl[row][cb+i+j] = l;
                    }
                }
            } else {
                const __nv_bfloat16 z = __float2bfloat16(0.f);
                #pragma unroll
                for (int i = 0; i < 16; i++){ sXh[row][cb+i] = z; sXl[row][cb+i] = z; }
            }
        }
        // ---- stage Wg/Wu tiles ----
        {
            const int kr = tid >> 3;
            const int cb = (tid & 7) * 8;
            const float* pg = wgp + (size_t)(k0 + kr) * N + n0 + cb;
            const float* pu = wup + (size_t)(k0 + kr) * N + n0 + cb;
            #pragma unroll
            for (int i = 0; i < 8; i += 4){
                float4 vg = *(const float4*)(pg + i);
                float4 vu = *(const float4*)(pu + i);
                float ag[4] = {vg.x,vg.y,vg.z,vg.w};
                float au[4] = {vu.x,vu.y,vu.z,vu.w};
                #pragma unroll
                for (int j = 0; j < 4; j++){
                    __nv_bfloat16 h, l;
                    bf16_split(ag[j], h, l); sWh[0][kr][cb+i+j] = h; sWl[0][kr][cb+i+j] = l;
                    bf16_split(au[j], h, l); sWh[1][kr][cb+i+j] = h; sWl[1][kr][cb+i+j] = l;
                }
            }
        }
        __syncthreads();
        // ---- compute ----
        #pragma unroll
        for (int ks = 0; ks < 2; ks++){
            uint32_t ah[2][4], al[2][4];
            #pragma unroll
            for (int mt = 0; mt < 2; mt++){
                const uint32_t aoff = (uint32_t)((mt*16*XS_STRIDE + ks*16) * 2);
                ldsm4(ah[mt][0],ah[mt][1],ah[mt][2],ah[mt][3], aBaseH + aoff);
                ldsm4(al[mt][0],al[mt][1],al[mt][2],al[mt][3], aBaseL + aoff);
            }
            {   // gate
                uint32_t bh[8], bl[8];
                #pragma unroll
                for (int hf = 0; hf < 2; hf++){
                    const uint32_t boff = (uint32_t)((ks*16*WS_STRIDE + hf*16) * 2);
                    ldsm4t(bh[hf*4+0],bh[hf*4+1],bh[hf*4+2],bh[hf*4+3], bgBaseH + boff);
                    ldsm4t(bl[hf*4+0],bl[hf*4+1],bl[hf*4+2],bl[hf*4+3], bgBaseL + boff);
                }
                #pragma unroll
                for (int mt = 0; mt < 2; mt++)
                    #pragma unroll
                    for (int ns = 0; ns < 4; ns++){
                        const int bi = (ns>>1)*4 + (ns&1)*2;
                        mma16816(accG[mt][ns], ah[mt][0],ah[mt][1],ah[mt][2],ah[mt][3], bh[bi], bh[bi+1]);
                        mma16816(accG[mt][ns], ah[mt][0],ah[mt][1],ah[mt][2],ah[mt][3], bl[bi], bl[bi+1]);
                        mma16816(accG[mt][ns], al[mt][0],al[mt][1],al[mt][2],al[mt][3], bh[bi], bh[bi+1]);
                    }
            }
            {   // up
                uint32_t bh[8], bl[8];
                #pragma unroll
                for (int hf = 0; hf < 2; hf++){
                    const uint32_t boff = (uint32_t)((ks*16*WS_STRIDE + hf*16) * 2);
                    ldsm4t(bh[hf*4+0],bh[hf*4+1],bh[hf*4+2],bh[hf*4+3], buBaseH + boff);
                    ldsm4t(bl[hf*4+0],bl[hf*4+1],bl[hf*4+2],bl[hf*4+3], buBaseL + boff);
                }
                #pragma unroll
                for (int mt = 0; mt < 2; mt++)
                    #pragma unroll
                    for (int ns = 0; ns < 4; ns++){
                        const int bi = (ns>>1)*4 + (ns&1)*2;
                        mma16816(accU[mt][ns], ah[mt][0],ah[mt][1],ah[mt][2],ah[mt][3], bh[bi], bh[bi+1]);
                        mma16816(accU[mt][ns], ah[mt][0],ah[mt][1],ah[mt][2],ah[mt][3], bl[bi], bl[bi+1]);
                        mma16816(accU[mt][ns], al[mt][0],al[mt][1],al[mt][2],al[mt][3], bh[bi], bh[bi+1]);
                    }
            }
        }
        __syncthreads();
    }
    // ---- epilogue: h = silu(g)*u ----
    const int gid = lane >> 2, tg = lane & 3;
    #pragma unroll
    for (int mt = 0; mt < 2; mt++){
        #pragma unroll
        for (int hf = 0; hf < 2; hf++){
            const int r = m0 + wm*32 + mt*16 + gid + hf*8;
            if (r < rows){
                #pragma unroll
                for (int ns = 0; ns < 4; ns++){
                    float g0 = accG[mt][ns][hf*2+0], g1 = accG[mt][ns][hf*2+1];
                    float u0 = accU[mt][ns][hf*2+0], u1 = accU[mt][ns][hf*2+1];
                    float h0 = g0 / (1.f + expf(-g0)) * u0;
                    float h1 = g1 / (1.f + expf(-g1)) * u1;
                    const int c = n0 + wn*32 + ns*8 + tg*2;
                    *(float2*)(hout + (size_t)r * N + c) = make_float2(h0, h1);
                }
            }
        }
    }
}

// ======= down grouped GEMM: Y = H @ Wd (per-assignment rows) =======
template<bool GATHER>
__global__ __launch_bounds__(256, 2)
void down_kernel(const float* __restrict__ Wd, float* __restrict__ outp, int K, int Mtot)
{
    __shared__ __align__(16) __nv_bfloat16 sAh[BM][XS_STRIDE];
    __shared__ __align__(16) __nv_bfloat16 sAl[BM][XS_STRIDE];
    __shared__ __align__(16) __nv_bfloat16 sBh[BK][WS_STRIDE];
    __shared__ __align__(16) __nv_bfloat16 sBl[BK][WS_STRIDE];
    __shared__ int s_orow[BM];

    const int e = blockIdx.z;
    const int rows = GATHER ? g_count[e] : Mtot;
    const int m0 = blockIdx.y * BM;
    if (m0 >= rows) return;
    const int n0 = blockIdx.x * BN;
    const int tid = threadIdx.x;
    const int lane = tid & 31, warp = tid >> 5;
    const int wm = warp & 3, wn = warp >> 2;

    const float* A   = GATHER ? (g_H + (size_t)e * CAP * F_INTER) : g_Hs;
    const float* wdp = GATHER ? (Wd + (size_t)e * F_INTER * D_MODEL) : Wd;
    float* outbase   = GATHER ? g_Y : outp;

    if (tid < BM){
        int r = m0 + tid;
        int orow = -1;
        if (r < rows) orow = GATHER ? g_rows[e*CAP + r] : r;
        s_orow[tid] = orow;
    }
    __syncthreads();

    float acc[2][4][4];
    #pragma unroll
    for (int a = 0; a < 2; a++)
        #pragma unroll
        for (int b = 0; b < 4; b++)
            #pragma unroll
            for (int c = 0; c < 4; c++) acc[a][b][c] = 0.f;

    const int aRow  = wm*32 + (lane & 15);
    const int aColB = 8 * (lane >> 4);
    const uint32_t aBaseH = smem_u32(&sAh[aRow][aColB]);
    const uint32_t aBaseL = smem_u32(&sAl[aRow][aColB]);
    const int bRow  = (lane & 15);
    const int bColB = wn*32 + 8*(lane >> 4);
    const uint32_t bBaseH = smem_u32(&sBh[bRow][bColB]);
    const uint32_t bBaseL = smem_u32(&sBl[bRow][bColB]);

    for (int k0 = 0; k0 < K; k0 += BK){
        {   // stage A (H rows)
            const int row = tid >> 1;
            const int cb  = (tid & 1) * 16;
            const int r = m0 + row;
            if (r < rows){
                const float* p = A + (size_t)r * K + k0 + cb;
                #pragma unroll
                for (int i = 0; i < 16; i += 4){
                    float4 v = *(const float4*)(p + i);
                    float vv[4] = {v.x, v.y, v.z, v.w};
                    #pragma unroll
                    for (int j = 0; j < 4; j++){
                        __nv_bfloat16 h, l; bf16_split(vv[j], h, l);
                        sAh[row][cb+i+j] = h; sAl[row][cb+i+j] = l;
                    }
                }
            } else {
                const __nv_bfloat16 z = __float2bfloat16(0.f);
                #pragma unroll
                for (int i = 0; i < 16; i++){ sAh[row][cb+i] = z; sAl[row][cb+i] = z; }
            }
        }
        {   // stage Wd
            const int kr = tid >> 3;
            const int cb = (tid & 7) * 8;
            const float* p = wdp + (size_t)(k0 + kr) * D_MODEL + n0 + cb;
            #pragma unroll
            for (int i = 0; i < 8; i += 4){
                float4 v = *(const float4*)(p + i);
                float vv[4] = {v.x,v.y,v.z,v.w};
                #pragma unroll
                for (int j = 0; j < 4; j++){
                    __nv_bfloat16 h, l; bf16_split(vv[j], h, l);
                    sBh[kr][cb+i+j] = h; sBl[kr][cb+i+j] = l;
                }
            }
        }
        __syncthreads();
        #pragma unroll
        for (int ks = 0; ks < 2; ks++){
            uint32_t ah[2][4], al[2][4];
            #pragma unroll
            for (int mt = 0; mt < 2; mt++){
                const uint32_t aoff = (uint32_t)((mt*16*XS_STRIDE + ks*16) * 2);
                ldsm4(ah[mt][0],ah[mt][1],ah[mt][2],ah[mt][3], aBaseH + aoff);
                ldsm4(al[mt][0],al[mt][1],al[mt][2],al[mt][3], aBaseL + aoff);
            }
            uint32_t bh[8], bl[8];
            #pragma unroll
            for (int hf = 0; hf < 2; hf++){
                const uint32_t boff = (uint32_t)((ks*16*WS_STRIDE + hf*16) * 2);
                ldsm4t(bh[hf*4+0],bh[hf*4+1],bh[hf*4+2],bh[hf*4+3], bBaseH + boff);
                ldsm4t(bl[hf*4+0],bl[hf*4+1],bl[hf*4+2],bl[hf*4+3], bBaseL + boff);
            }
            #pragma unroll
            for (int mt = 0; mt < 2; mt++)
                #pragma unroll
                for (int ns = 0; ns < 4; ns++){
                    const int bi = (ns>>1)*4 + (ns&1)*2;
                    mma16816(acc[mt][ns], ah[mt][0],ah[mt][1],ah[mt][2],ah[mt][3], bh[bi], bh[bi+1]);
                    mma16816(acc[mt][ns], ah[mt][0],ah[mt][1],ah[mt][2],ah[mt][3], bl[bi], bl[bi+1]);
                    mma16816(acc[mt][ns], al[mt][0],al[mt][1],al[mt][2],al[mt][3], bh[bi], bh[bi+1]);
                }
        }
        __syncthreads();
    }
    // epilogue: scatter to output rows
    const int gid = lane >> 2, tg = lane & 3;
    #pragma unroll
    for (int mt = 0; mt < 2; mt++){
        #pragma unroll
        for (int hf = 0; hf < 2; hf++){
            const int rl = wm*32 + mt*16 + gid + hf*8;
            const int orow = s_orow[rl];
            if (orow >= 0){
                #pragma unroll
                for (int ns = 0; ns < 4; ns++){
                    const int c = n0 + wn*32 + ns*8 + tg*2;
                    *(float2*)(outbase + (size_t)orow * D_MODEL + c) =
                        make_float2(acc[mt][ns][hf*2+0], acc[mt][ns][hf*2+1]);
                }
            }
        }
    }
}

// ======= combine: out = shared_out + sum_k w_k * Y[assignment] =======
__global__ void combine_kernel(float* __restrict__ out)
{
    const int t = blockIdx.x;
    __shared__ float sw[TOPK];
    __shared__ int sv[TOPK];
    if (threadIdx.x < TOPK){
        sw[threadIdx.x] = g_topk_w[t*TOPK + threadIdx.x];
        sv[threadIdx.x] = (g_pos[t*TOPK + threadIdx.x] < CAP) ? 1 : 0;
    }
    __syncthreads();
    for (int d = threadIdx.x * 4; d < D_MODEL; d += 256*4){
        float4 accv = *(float4*)(out + (size_t)t*D_MODEL + d);
        #pragma unroll
        for (int k = 0; k < TOPK; k++){
            if (sv[k]){
                const float4 yv = *(const float4*)(g_Y + ((size_t)(t*TOPK + k))*D_MODEL + d);
                const float w = sw[k];
                accv.x += w*yv.x; accv.y += w*yv.y; accv.z += w*yv.z; accv.w += w*yv.w;
            }
        }
        *(float4*)(out + (size_t)t*D_MODEL + d) = accv;
    }
}

// ---------------- launcher ----------------
extern "C" void kernel_launch(void* const* d_in, const int* in_sizes, int n_in,
                              void* d_out, int out_size)
{
    (void)in_sizes; (void)n_in; (void)out_size;
    const float* x   = (const float*)d_in[0];
    const float* wgr = (const float*)d_in[1];
    const float* wg  = (const float*)d_in[2];
    const float* wu  = (const float*)d_in[3];
    const float* wd  = (const float*)d_in[4];
    const float* wsg = (const float*)d_in[5];
    const float* wsu = (const float*)d_in[6];
    const float* wsd = (const float*)d_in[7];
    float* out = (float*)d_out;

    router_kernel<<<T_TOKENS, 128>>>(x, wgr);
    dispatch_kernel<<<1, 1024>>>();
    // expert gate/up SwiGLU  -> g_H
    gateup_kernel<true ><<<dim3(F_INTER/BN,  CAP/BM,      N_EXP), 256>>>(x, wg,  wu,  F_INTER,  0);
    // shared-expert gate/up  -> g_Hs
    gateup_kernel<false><<<dim3(FS_INTER/BN, T_TOKENS/BM, 1    ), 256>>>(x, wsg, wsu, FS_INTER, T_TOKENS);
    // expert down -> g_Y (per-assignment rows)
    down_kernel<true ><<<dim3(D_MODEL/BN, CAP/BM,      N_EXP), 256>>>(wd,  nullptr, F_INTER,  0);
    // shared down -> d_out (fully covers output)
    down_kernel<false><<<dim3(D_MODEL/BN, T_TOKENS/BM, 1    ), 256>>>(wsd, out,     FS_INTER, T_TOKENS);
    // final combine
    combine_kernel<<<T_TOKENS, 256>>>(out);
}

// round 15
// speedup vs baseline: 1.1224x; 1.1224x over previous
#include <cuda_runtime.h>
#include <cuda_bf16.h>
#include <cstdint>
#include <math.h>

// ---------------- problem constants ----------------
#define T_TOKENS 2048
#define D_MODEL  2048
#define F_INTER  1408
#define FS_INTER 2816
#define N_EXP    32
#define TOPK     6
#define CAP      768              // 2 * (2048*6/32)
#define NASSIGN  (T_TOKENS*TOPK)  // 12288

static const size_t EDF = (size_t)N_EXP * D_MODEL * F_INTER;   // 92,274,688
static const size_t DFS = (size_t)D_MODEL * FS_INTER;          // 5,767,168

// ---------------- GEMM tiling ----------------
#define BM 128
#define BN 64
#define BK 16
#define AS 24      // A smem row stride (elems) : 48B rows, conflict-free
#define BS 72      // B smem row stride (elems) : 144B rows, conflict-free

// ---------------- device scratch ----------------
__device__ int   g_topk_idx[NASSIGN];
__device__ float g_topk_w[NASSIGN];
__device__ int   g_pos[NASSIGN];
__device__ int   g_rows[N_EXP*CAP];
__device__ int   g_count[N_EXP];

// split bf16 planes (hi / lo)
__device__ __nv_bfloat16 g_xh [(size_t)T_TOKENS*D_MODEL];
__device__ __nv_bfloat16 g_xl [(size_t)T_TOKENS*D_MODEL];
__device__ __nv_bfloat16 g_wgh[(size_t)N_EXP*D_MODEL*F_INTER];
__device__ __nv_bfloat16 g_wgl[(size_t)N_EXP*D_MODEL*F_INTER];
__device__ __nv_bfloat16 g_wuh[(size_t)N_EXP*D_MODEL*F_INTER];
__device__ __nv_bfloat16 g_wul[(size_t)N_EXP*D_MODEL*F_INTER];
__device__ __nv_bfloat16 g_wdh[(size_t)N_EXP*D_MODEL*F_INTER];
__device__ __nv_bfloat16 g_wdl[(size_t)N_EXP*D_MODEL*F_INTER];
__device__ __nv_bfloat16 g_sgh[(size_t)D_MODEL*FS_INTER];
__device__ __nv_bfloat16 g_sgl[(size_t)D_MODEL*FS_INTER];
__device__ __nv_bfloat16 g_suh[(size_t)D_MODEL*FS_INTER];
__device__ __nv_bfloat16 g_sul[(size_t)D_MODEL*FS_INTER];
__device__ __nv_bfloat16 g_sdh[(size_t)D_MODEL*FS_INTER];
__device__ __nv_bfloat16 g_sdl[(size_t)D_MODEL*FS_INTER];

// intermediates (H stored as split planes; Y fp32)
__device__ __nv_bfloat16 g_Hh [(size_t)N_EXP*CAP*F_INTER];
__device__ __nv_bfloat16 g_Hl [(size_t)N_EXP*CAP*F_INTER];
__device__ __nv_bfloat16 g_Hsh[(size_t)T_TOKENS*FS_INTER];
__device__ __nv_bfloat16 g_Hsl[(size_t)T_TOKENS*FS_INTER];
__device__ float g_Y[(size_t)NASSIGN*D_MODEL];

// ---------------- helpers ----------------
__device__ __forceinline__ uint32_t smem_u32(const void* p){
    return (uint32_t)__cvta_generic_to_shared(p);
}
__device__ __forceinline__ void cp16(uint32_t dst, const void* src, bool pred){
    int sz = pred ? 16 : 0;
    asm volatile("cp.async.cg.shared.global [%0],[%1],16,%2;\n"::"r"(dst),"l"(src),"r"(sz));
}
__device__ __forceinline__ void cp_commit(){ asm volatile("cp.async.commit_group;\n"::); }
template<int NW> __device__ __forceinline__ void cp_wait(){
    asm volatile("cp.async.wait_group %0;\n"::"n"(NW));
}
__device__ __forceinline__ void ldsm4(uint32_t &r0,uint32_t &r1,uint32_t &r2,uint32_t &r3, uint32_t addr){
    asm volatile("ldmatrix.sync.aligned.m8n8.x4.shared.b16 {%0,%1,%2,%3},[%4];\n"
                 :"=r"(r0),"=r"(r1),"=r"(r2),"=r"(r3):"r"(addr));
}
__device__ __forceinline__ void ldsm4t(uint32_t &r0,uint32_t &r1,uint32_t &r2,uint32_t &r3, uint32_t addr){
    asm volatile("ldmatrix.sync.aligned.m8n8.x4.trans.shared.b16 {%0,%1,%2,%3},[%4];\n"
                 :"=r"(r0),"=r"(r1),"=r"(r2),"=r"(r3):"r"(addr));
}
__device__ __forceinline__ void mma16816(float* c,
        uint32_t a0,uint32_t a1,uint32_t a2,uint32_t a3, uint32_t b0,uint32_t b1){
    asm volatile("mma.sync.aligned.m16n8k16.row.col.f32.bf16.bf16.f32 "
                 "{%0,%1,%2,%3},{%4,%5,%6,%7},{%8,%9},{%0,%1,%2,%3};\n"
                 :"+f"(c[0]),"+f"(c[1]),"+f"(c[2]),"+f"(c[3])
                 :"r"(a0),"r"(a1),"r"(a2),"r"(a3),"r"(b0),"r"(b1));
}
__device__ __forceinline__ void split2_store(float v0, float v1,
                                             __nv_bfloat16* hp, __nv_bfloat16* lp){
    __nv_bfloat162 h = __float22bfloat162_rn(make_float2(v0, v1));
    float2 hf = __bfloat1622float2(h);
    __nv_bfloat162 l = __float22bfloat162_rn(make_float2(v0 - hf.x, v1 - hf.y));
    *(__nv_bfloat162*)hp = h;
    *(__nv_bfloat162*)lp = l;
}

// ================= split: fp32 -> bf16 hi/lo planes =================
__global__ void split_kernel(const float* __restrict__ in, long long n, int which)
{
    __nv_bfloat16 *hp, *lp;
    switch (which){
        case 0: hp = g_xh;  lp = g_xl;  break;
        case 1: hp = g_wgh; lp = g_wgl; break;
        case 2: hp = g_wuh; lp = g_wul; break;
        case 3: hp = g_wdh; lp = g_wdl; break;
        case 4: hp = g_sgh; lp = g_sgl; break;
        case 5: hp = g_suh; lp = g_sul; break;
        default:hp = g_sdh; lp = g_sdl; break;
    }
    long long i = ((long long)blockIdx.x * blockDim.x + threadIdx.x) * 4;
    if (i < n){
        float4 v = *(const float4*)(in + i);
        __nv_bfloat162 h01 = __float22bfloat162_rn(make_float2(v.x, v.y));
        __nv_bfloat162 h23 = __float22bfloat162_rn(make_float2(v.z, v.w));
        float2 f01 = __bfloat1622float2(h01), f23 = __bfloat1622float2(h23);
        __nv_bfloat162 l01 = __float22bfloat162_rn(make_float2(v.x - f01.x, v.y - f01.y));
        __nv_bfloat162 l23 = __float22bfloat162_rn(make_float2(v.z - f23.x, v.w - f23.y));
        *(__nv_bfloat162*)(hp + i)     = h01;
        *(__nv_bfloat162*)(hp + i + 2) = h23;
        *(__nv_bfloat162*)(lp + i)     = l01;
        *(__nv_bfloat162*)(lp + i + 2) = l23;
    }
}

// ================= router: softmax + top-6 =================
__global__ void router_kernel(const float* __restrict__ x, const float* __restrict__ wg)
{
    const int t = blockIdx.x;
    const int tid = threadIdx.x;               // 128 threads
    const int warp = tid >> 5, lane = tid & 31;
    __shared__ float s_sc[N_EXP];
    const float* xr = x + (size_t)t * D_MODEL;
    for (int e = warp; e < N_EXP; e += 4){
        const float* w = wg + (size_t)e * D_MODEL;
        float acc = 0.f;
        for (int d = lane * 4; d < D_MODEL; d += 128){
            float4 xv = *(const float4*)(xr + d);
            float4 wv = *(const float4*)(w + d);
            acc += xv.x*wv.x + xv.y*wv.y + xv.z*wv.z + xv.w*wv.w;
        }
        #pragma unroll
        for (int o = 16; o; o >>= 1) acc += __shfl_xor_sync(0xffffffffu, acc, o);
        if (lane == 0) s_sc[e] = acc;
    }
    __syncthreads();
    if (warp == 0){
        float v = s_sc[lane];
        float m = v;
        #pragma unroll
        for (int o = 16; o; o >>= 1) m = fmaxf(m, __shfl_xor_sync(0xffffffffu, m, o));
        float ev = expf(v - m);
        float Z = ev;
        #pragma unroll
        for (int o = 16; o; o >>= 1) Z += __shfl_xor_sync(0xffffffffu, Z, o);
        float s = ev / Z;
        float cur = s;
        float sum6 = 0.f;
        int   sel_idx = 0; float sel_val = 0.f;
        #pragma unroll
        for (int k = 0; k < TOPK; k++){
            float bv = cur; int bi = lane;
            #pragma unroll
            for (int o = 16; o; o >>= 1){
                float ovv = __shfl_xor_sync(0xffffffffu, bv, o);
                int   oi  = __shfl_xor_sync(0xffffffffu, bi, o);
                if (ovv > bv || (ovv == bv && oi < bi)){ bv = ovv; bi = oi; }
            }
            sum6 += bv;
            if (lane == k){ sel_idx = bi; sel_val = bv; }
            if (lane == bi) cur = -1.f;
        }
        if (lane < TOPK){
            g_topk_idx[t*TOPK + lane] = sel_idx;
            g_topk_w [t*TOPK + lane] = sel_val / (sum6 + 1e-20f);
        }
    }
}

// ======= dispatch: flattened-order positions =======
__global__ void dispatch_kernel()
{
    __shared__ int s_idx[NASSIGN];   // 48 KB
    for (int i = threadIdx.x; i < NASSIGN; i += 1024) s_idx[i] = g_topk_idx[i];
    __syncthreads();
    const int warp = threadIdx.x >> 5;   // expert id
    const int lane = threadIdx.x & 31;
    int count = 0;
    for (int base = 0; base < NASSIGN; base += 32){
        int eidx = s_idx[base + lane];
        unsigned msk = __ballot_sync(0xffffffffu, eidx == warp);
        if (eidx == warp){
            int p = count + __popc(msk & ((1u << lane) - 1u));
            g_pos[base + lane] = p;
            if (p < CAP) g_rows[warp*CAP + p] = base + lane;
        }
        count += __popc(msk);
    }
    if (lane == 0) g_count[warp] = (count < CAP) ? count : CAP;
}

// ======= fused gate/up SwiGLU grouped GEMM — cp.async pipelined, pure bf16 =======
template<bool GATHER>
__global__ __launch_bounds__(256, 2)
void gateup_kernel(int N, int Mtot)
{
    __shared__ __align__(16) __nv_bfloat16 sAh[2][BM][AS];
    __shared__ __align__(16) __nv_bfloat16 sAl[2][BM][AS];
    __shared__ __align__(16) __nv_bfloat16 sBh[2][2][BK][BS];   // [buf][gate/up]
    __shared__ __align__(16) __nv_bfloat16 sBl[2][2][BK][BS];
    __shared__ int s_tok[BM];

    const int e = blockIdx.z;
    const int rows = GATHER ? g_count[e] : Mtot;
    const int m0 = blockIdx.y * BM;
    if (m0 >= rows) return;
    const int n0 = blockIdx.x * BN;
    const int tid = threadIdx.x;
    const int lane = tid & 31, warp = tid >> 5;
    const int wm = warp & 3, wn = warp >> 2;

    const __nv_bfloat16* wgh = GATHER ? g_wgh + (size_t)e*D_MODEL*N : g_sgh;
    const __nv_bfloat16* wgl = GATHER ? g_wgl + (size_t)e*D_MODEL*N : g_sgl;
    const __nv_bfloat16* wuh = GATHER ? g_wuh + (size_t)e*D_MODEL*N : g_suh;
    const __nv_bfloat16* wul = GATHER ? g_wul + (size_t)e*D_MODEL*N : g_sul;
    __nv_bfloat16* hh = GATHER ? g_Hh + (size_t)e*CAP*N : g_Hsh;
    __nv_bfloat16* hl = GATHER ? g_Hl + (size_t)e*CAP*N : g_Hsl;

    if (tid < BM){
        int r = m0 + tid;
        s_tok[tid] = (r < rows) ? (GATHER ? (g_rows[e*CAP + r] / TOPK) : r) : -1;
    }
    __syncthreads();

    // ---- staging setup ----
    const int arow = tid >> 1, ac8 = (tid & 1) * 8;
    const int bmat = tid >> 7, bu = tid & 127;
    const int brow = bu >> 3, bc8 = (bu & 7) * 8;
    const uint32_t aDstH = smem_u32(&sAh[0][arow][ac8]);
    const uint32_t aDstL = smem_u32(&sAl[0][arow][ac8]);
    const uint32_t bDstH = smem_u32(&sBh[0][bmat][brow][bc8]);
    const uint32_t bDstL = smem_u32(&sBl[0][bmat][brow][bc8]);
    const int atok = s_tok[arow];
    const bool apred = (atok >= 0);
    const size_t aoff = (size_t)(apred ? atok : 0) * D_MODEL + ac8;
    const __nv_bfloat16* bSrcH = (bmat ? wuh : wgh) + (size_t)brow * N + n0 + bc8;
    const __nv_bfloat16* bSrcL = (bmat ? wul : wgl) + (size_t)brow * N + n0 + bc8;
    const uint32_t ABUF = (uint32_t)(BM*AS*2);
    const uint32_t BBUF = (uint32_t)(2*BK*BS*2);

    auto stage = [&](int kt, int bsel){
        const int k0 = kt * BK;
        const uint32_t ao = bsel ? ABUF : 0u;
        const uint32_t bo = bsel ? BBUF : 0u;
        cp16(aDstH + ao, g_xh + aoff + k0, apred);
        cp16(aDstL + ao, g_xl + aoff + k0, apred);
        cp16(bDstH + bo, bSrcH + (size_t)k0 * N, true);
        cp16(bDstL + bo, bSrcL + (size_t)k0 * N, true);
    };

    // ---- fragment bases ----
    const int aRow = wm*32 + (lane & 15);
    const int aCol = 8 * (lane >> 4);
    const uint32_t aFH = smem_u32(&sAh[0][aRow][aCol]);
    const uint32_t aFL = smem_u32(&sAl[0][aRow][aCol]);
    const int bRow = lane & 15;
    const int bCol = wn*32 + 8*(lane >> 4);
    const uint32_t bgFH = smem_u32(&sBh[0][0][bRow][bCol]);
    const uint32_t bgFL = smem_u32(&sBl[0][0][bRow][bCol]);
    const uint32_t buFH = smem_u32(&sBh[0][1][bRow][bCol]);
    const uint32_t buFL = smem_u32(&sBl[0][1][bRow][bCol]);

    float accG[2][4][4] = {};
    float accU[2][4][4] = {};

    const int KT = D_MODEL / BK;
    stage(0, 0); cp_commit();
    for (int kt = 0; kt < KT; kt++){
        const int bsel = kt & 1;
        if (kt + 1 < KT){ stage(kt + 1, bsel ^ 1); cp_commit(); cp_wait<1>(); }
        else cp_wait<0>();
        __syncthreads();
        const uint32_t ao = bsel ? ABUF : 0u;
        const uint32_t bo = bsel ? BBUF : 0u;
        uint32_t ah[2][4], al[2][4];
        #pragma unroll
        for (int mt = 0; mt < 2; mt++){
            const uint32_t o = ao + (uint32_t)(mt*16*AS*2);
            ldsm4(ah[mt][0],ah[mt][1],ah[mt][2],ah[mt][3], aFH + o);
            ldsm4(al[mt][0],al[mt][1],al[mt][2],al[mt][3], aFL + o);
        }
        {   // gate
            uint32_t bh[8], bl[8];
            #pragma unroll
            for (int hf = 0; hf < 2; hf++){
                const uint32_t o = bo + (uint32_t)(hf*16*2);
                ldsm4t(bh[hf*4+0],bh[hf*4+1],bh[hf*4+2],bh[hf*4+3], bgFH + o);
                ldsm4t(bl[hf*4+0],bl[hf*4+1],bl[hf*4+2],bl[hf*4+3], bgFL + o);
            }
            #pragma unroll
            for (int mt = 0; mt < 2; mt++)
                #pragma unroll
                for (int ns = 0; ns < 4; ns++){
                    const int bi = (ns>>1)*4 + (ns&1)*2;
                    mma16816(accG[mt][ns], ah[mt][0],ah[mt][1],ah[mt][2],ah[mt][3], bh[bi], bh[bi+1]);
                    mma16816(accG[mt][ns], ah[mt][0],ah[mt][1],ah[mt][2],ah[mt][3], bl[bi], bl[bi+1]);
                    mma16816(accG[mt][ns], al[mt][0],al[mt][1],al[mt][2],al[mt][3], bh[bi], bh[bi+1]);
                }
        }
        {   // up
            uint32_t bh[8], bl[8];
            #pragma unroll
            for (int hf = 0; hf < 2; hf++){
                const uint32_t o = bo + (uint32_t)(hf*16*2);
                ldsm4t(bh[hf*4+0],bh[hf*4+1],bh[hf*4+2],bh[hf*4+3], buFH + o);
                ldsm4t(bl[hf*4+0],bl[hf*4+1],bl[hf*4+2],bl[hf*4+3], buFL + o);
            }
            #pragma unroll
            for (int mt = 0; mt < 2; mt++)
                #pragma unroll
                for (int ns = 0; ns < 4; ns++){
                    const int bi = (ns>>1)*4 + (ns&1)*2;
                    mma16816(accU[mt][ns], ah[mt][0],ah[mt][1],ah[mt][2],ah[mt][3], bh[bi], bh[bi+1]);
                    mma16816(accU[mt][ns], ah[mt][0],ah[mt][1],ah[mt][2],ah[mt][3], bl[bi], bl[bi+1]);
                    mma16816(accU[mt][ns], al[mt][0],al[mt][1],al[mt][2],al[mt][3], bh[bi], bh[bi+1]);
                }
        }
        __syncthreads();
    }

    // ---- epilogue: h = silu(g)*u, written as split planes ----
    const int gid = lane >> 2, tg = lane & 3;
    #pragma unroll
    for (int mt = 0; mt < 2; mt++){
        #pragma unroll
        for (int hf = 0; hf < 2; hf++){
            const int r = m0 + wm*32 + mt*16 + gid + hf*8;
            if (r < rows){
                #pragma unroll
                for (int ns = 0; ns < 4; ns++){
                    float g0 = accG[mt][ns][hf*2+0], g1 = accG[mt][ns][hf*2+1];
                    float u0 = accU[mt][ns][hf*2+0], u1 = accU[mt][ns][hf*2+1];
                    float h0 = g0 / (1.f + expf(-g0)) * u0;
                    float h1 = g1 / (1.f + expf(-g1)) * u1;
                    const int c = n0 + wn*32 + ns*8 + tg*2;
                    const size_t idx = (size_t)r * N + c;
                    split2_store(h0, h1, hh + idx, hl + idx);
                }
            }
        }
    }
}

// ======= down grouped GEMM — cp.async pipelined, pure bf16 =======
template<bool GATHER>
__global__ __launch_bounds__(256, 2)
void down_kernel(float* __restrict__ outp, int K, int Mtot)
{
    __shared__ __align__(16) __nv_bfloat16 sAh[2][BM][AS];
    __shared__ __align__(16) __nv_bfloat16 sAl[2][BM][AS];
    __shared__ __align__(16) __nv_bfloat16 sBh[2][BK][BS];
    __shared__ __align__(16) __nv_bfloat16 sBl[2][BK][BS];
    __shared__ int s_orow[BM];

    const int e = blockIdx.z;
    const int rows = GATHER ? g_count[e] : Mtot;
    const int m0 = blockIdx.y * BM;
    if (m0 >= rows) return;
    const int n0 = blockIdx.x * BN;
    const int tid = threadIdx.x;
    const int lane = tid & 31, warp = tid >> 5;
    const int wm = warp & 3, wn = warp >> 2;

    const __nv_bfloat16* Ahp = GATHER ? g_Hh + (size_t)e*CAP*K : g_Hsh;
    const __nv_bfloat16* Alp = GATHER ? g_Hl + (size_t)e*CAP*K : g_Hsl;
    const __nv_bfloat16* Bhp = GATHER ? g_wdh + (size_t)e*(size_t)K*D_MODEL : g_sdh;
    const __nv_bfloat16* Blp = GATHER ? g_wdl + (size_t)e*(size_t)K*D_MODEL : g_sdl;
    float* outbase = GATHER ? g_Y : outp;

    if (tid < BM){
        int r = m0 + tid;
        s_orow[tid] = (r < rows) ? (GATHER ? g_rows[e*CAP + r] : r) : -1;
    }
    __syncthreads();

    // staging setup
    const int arow = tid >> 1, ac8 = (tid & 1) * 8;
    const bool apred = (m0 + arow) < rows;
    const size_t aoff = (size_t)(apred ? (m0 + arow) : 0) * K + ac8;
    const int bpl = tid >> 7, bu = tid & 127;
    const int brow = bu >> 3, bc8 = (bu & 7) * 8;
    const uint32_t aDstH = smem_u32(&sAh[0][arow][ac8]);
    const uint32_t aDstL = smem_u32(&sAl[0][arow][ac8]);
    const uint32_t bDst = bpl ? smem_u32(&sBl[0][brow][bc8]) : smem_u32(&sBh[0][brow][bc8]);
    const __nv_bfloat16* bSrc = (bpl ? Blp : Bhp) + (size_t)brow * D_MODEL + n0 + bc8;
    const uint32_t ABUF = (uint32_t)(BM*AS*2);
    const uint32_t BBUF = (uint32_t)(BK*BS*2);

    auto stage = [&](int kt, int bsel){
        const int k0 = kt * BK;
        const uint32_t ao = bsel ? ABUF : 0u;
        const uint32_t bo = bsel ? BBUF : 0u;
        cp16(aDstH + ao, Ahp + aoff + k0, apred);
        cp16(aDstL + ao, Alp + aoff + k0, apred);
        cp16(bDst + bo, bSrc + (size_t)k0 * D_MODEL, true);
    };

    const int aRow = wm*32 + (lane & 15);
    const int aCol = 8 * (lane >> 4);
    const uint32_t aFH = smem_u32(&sAh[0][aRow][aCol]);
    const uint32_t aFL = smem_u32(&sAl[0][aRow][aCol]);
    const int bRow = lane & 15;
    const int bCol = wn*32 + 8*(lane >> 4);
    const uint32_t bFH = smem_u32(&sBh[0][bRow][bCol]);
    const uint32_t bFL = smem_u32(&sBl[0][bRow][bCol]);

    float acc[2][4][4] = {};

    const int KT = K / BK;
    stage(0, 0); cp_commit();
    for (int kt = 0; kt < KT; kt++){
        const int bsel = kt & 1;
        if (kt + 1 < KT){ stage(kt + 1, bsel ^ 1); cp_commit(); cp_wait<1>(); }
        else cp_wait<0>();
        __syncthreads();
        const uint32_t ao = bsel ? ABUF : 0u;
        const uint32_t bo = bsel ? BBUF : 0u;
        uint32_t ah[2][4], al[2][4];
        #pragma unroll
        for (int mt = 0; mt < 2; mt++){
            const uint32_t o = ao + (uint32_t)(mt*16*AS*2);
            ldsm4(ah[mt][0],ah[mt][1],ah[mt][2],ah[mt][3], aFH + o);
            ldsm4(al[mt][0],al[mt][1],al[mt][2],al[mt][3], aFL + o);
        }
        uint32_t bh[8], bl[8];
        #pragma unroll
        for (int hf = 0; hf < 2; hf++){
            const uint32_t o = bo + (uint32_t)(hf*16*2);
            ldsm4t(bh[hf*4+0],bh[hf*4+1],bh[hf*4+2],bh[hf*4+3], bFH + o);
            ldsm4t(bl[hf*4+0],bl[hf*4+1],bl[hf*4+2],bl[hf*4+3], bFL + o);
        }
        #pragma unroll
        for (int mt = 0; mt < 2; mt++)
            #pragma unroll
            for (int ns = 0; ns < 4; ns++){
                const int bi = (ns>>1)*4 + (ns&1)*2;
                mma16816(acc[mt][ns], ah[mt][0],ah[mt][1],ah[mt][2],ah[mt][3], bh[bi], bh[bi+1]);
                mma16816(acc[mt][ns], ah[mt][0],ah[mt][1],ah[mt][2],ah[mt][3], bl[bi], bl[bi+1]);
                mma16816(acc[mt][ns], al[mt][0],al[mt][1],al[mt][2],al[mt][3], bh[bi], bh[bi+1]);
            }
        __syncthreads();
    }

    // epilogue: scatter
    const int gid = lane >> 2, tg = lane & 3;
    #pragma unroll
    for (int mt = 0; mt < 2; mt++){
        #pragma unroll
        for (int hf = 0; hf < 2; hf++){
            const int rl = wm*32 + mt*16 + gid + hf*8;
            const int orow = s_orow[rl];
            if (orow >= 0){
                #pragma unroll
                for (int ns = 0; ns < 4; ns++){
                    const int c = n0 + wn*32 + ns*8 + tg*2;
                    *(float2*)(outbase + (size_t)orow * D_MODEL + c) =
                        make_float2(acc[mt][ns][hf*2+0], acc[mt][ns][hf*2+1]);
                }
            }
        }
    }
}

// ======= combine: out = shared_out + sum_k w_k * Y[assignment] =======
__global__ void combine_kernel(float* __restrict__ out)
{
    const int t = blockIdx.x;
    __shared__ float sw[TOPK];
    __shared__ int sv[TOPK];
    if (threadIdx.x < TOPK){
        sw[threadIdx.x] = g_topk_w[t*TOPK + threadIdx.x];
        sv[threadIdx.x] = (g_pos[t*TOPK + threadIdx.x] < CAP) ? 1 : 0;
    }
    __syncthreads();
    for (int d = threadIdx.x * 4; d < D_MODEL; d += 256*4){
        float4 accv = *(float4*)(out + (size_t)t*D_MODEL + d);
        #pragma unroll
        for (int k = 0; k < TOPK; k++){
            if (sv[k]){
                const float4 yv = *(const float4*)(g_Y + ((size_t)(t*TOPK + k))*D_MODEL + d);
                const float w = sw[k];
                accv.x += w*yv.x; accv.y += w*yv.y; accv.z += w*yv.z; accv.w += w*yv.w;
            }
        }
        *(float4*)(out + (size_t)t*D_MODEL + d) = accv;
    }
}

// ---------------- launcher ----------------
static inline int split_grid(long long n){ return (int)((n/4 + 255) / 256); }

extern "C" void kernel_launch(void* const* d_in, const int* in_sizes, int n_in,
                              void* d_out, int out_size)
{
    (void)in_sizes; (void)n_in; (void)out_size;
    const float* x   = (const float*)d_in[0];
    const float* wgr = (const float*)d_in[1];
    const float* wg  = (const float*)d_in[2];
    const float* wu  = (const float*)d_in[3];
    const float* wd  = (const float*)d_in[4];
    const float* wsg = (const float*)d_in[5];
    const float* wsu = (const float*)d_in[6];
    const float* wsd = (const float*)d_in[7];
    float* out = (float*)d_out;

    const long long nX  = (long long)T_TOKENS * D_MODEL;
    const long long nW  = (long long)N_EXP * D_MODEL * F_INTER;
    const long long nS  = (long long)D_MODEL * FS_INTER;

    split_kernel<<<split_grid(nX), 256>>>(x,   nX, 0);
    split_kernel<<<split_grid(nW), 256>>>(wg,  nW, 1);
    split_kernel<<<split_grid(nW), 256>>>(wu,  nW, 2);
    split_kernel<<<split_grid(nW), 256>>>(wd,  nW, 3);
    split_kernel<<<split_grid(nS), 256>>>(wsg, nS, 4);
    split_kernel<<<split_grid(nS), 256>>>(wsu, nS, 5);
    split_kernel<<<split_grid(nS), 256>>>(wsd, nS, 6);

    router_kernel<<<T_TOKENS, 128>>>(x, wgr);
    dispatch_kernel<<<1, 1024>>>();

    // expert gate/up SwiGLU -> H planes
    gateup_kernel<true ><<<dim3(F_INTER/BN,  CAP/BM,      N_EXP), 256>>>(F_INTER,  0);
    // shared-expert gate/up -> Hs planes
    gateup_kernel<false><<<dim3(FS_INTER/BN, T_TOKENS/BM, 1    ), 256>>>(FS_INTER, T_TOKENS);
    // expert down -> g_Y
    down_kernel<true ><<<dim3(D_MODEL/BN, CAP/BM,      N_EXP), 256>>>(nullptr, F_INTER,  0);
    // shared down -> d_out
    down_kernel<false><<<dim3(D_MODEL/BN, T_TOKENS/BM, 1    ), 256>>>(out,     FS_INTER, T_TOKENS);
    // final combine
    combine_kernel<<<T_TOKENS, 256>>>(out);
}

// round 17
// speedup vs baseline: 1.1753x; 1.0471x over previous
#include <cuda_runtime.h>
#include <cuda_bf16.h>
#include <cstdint>
#include <math.h>

// ---------------- problem constants ----------------
#define T_TOKENS 2048
#define D_MODEL  2048
#define F_INTER  1408
#define FS_INTER 2816
#define N_EXP    32
#define TOPK     6
#define CAP      768
#define NASSIGN  (T_TOKENS*TOPK)

// ---------------- GEMM tiling ----------------
#define BM 128
#define BN 64
#define BK 32
#define AS 40      // A smem row stride (elems): 80B rows, ldmatrix conflict-free
#define BS 72      // B smem row stride (elems): 144B rows, conflict-free

// gateup per-buffer smem layout (bytes)
#define GU_AH   0
#define GU_AL   10240
#define GU_BGH  20480
#define GU_BGL  25088
#define GU_BUH  29696
#define GU_BUL  34304
#define GU_BUFSZ 38912
#define GU_SMEM (2*GU_BUFSZ + 512)
// down per-buffer smem layout
#define DN_AH   0
#define DN_AL   10240
#define DN_BH   20480
#define DN_BL   25088
#define DN_BUFSZ 29696
#define DN_SMEM (2*DN_BUFSZ + 512 + 512)

// ---------------- device scratch ----------------
__device__ int   g_topk_idx[NASSIGN];
__device__ float g_topk_w[NASSIGN];
__device__ int   g_pos[NASSIGN];
__device__ int   g_rows[N_EXP*CAP];
__device__ int   g_count[N_EXP];

// split bf16 planes (hi / lo)
__device__ __nv_bfloat16 g_xh [(size_t)T_TOKENS*D_MODEL];
__device__ __nv_bfloat16 g_xl [(size_t)T_TOKENS*D_MODEL];
__device__ __nv_bfloat16 g_wgh[(size_t)N_EXP*D_MODEL*F_INTER];
__device__ __nv_bfloat16 g_wgl[(size_t)N_EXP*D_MODEL*F_INTER];
__device__ __nv_bfloat16 g_wuh[(size_t)N_EXP*D_MODEL*F_INTER];
__device__ __nv_bfloat16 g_wul[(size_t)N_EXP*D_MODEL*F_INTER];
__device__ __nv_bfloat16 g_wdh[(size_t)N_EXP*D_MODEL*F_INTER];
__device__ __nv_bfloat16 g_wdl[(size_t)N_EXP*D_MODEL*F_INTER];
__device__ __nv_bfloat16 g_sgh[(size_t)D_MODEL*FS_INTER];
__device__ __nv_bfloat16 g_sgl[(size_t)D_MODEL*FS_INTER];
__device__ __nv_bfloat16 g_suh[(size_t)D_MODEL*FS_INTER];
__device__ __nv_bfloat16 g_sul[(size_t)D_MODEL*FS_INTER];
__device__ __nv_bfloat16 g_sdh[(size_t)D_MODEL*FS_INTER];
__device__ __nv_bfloat16 g_sdl[(size_t)D_MODEL*FS_INTER];

// intermediates (H stored as split planes)
__device__ __nv_bfloat16 g_Hh [(size_t)N_EXP*CAP*F_INTER];
__device__ __nv_bfloat16 g_Hl [(size_t)N_EXP*CAP*F_INTER];
__device__ __nv_bfloat16 g_Hsh[(size_t)T_TOKENS*FS_INTER];
__device__ __nv_bfloat16 g_Hsl[(size_t)T_TOKENS*FS_INTER];

// ---------------- helpers ----------------
__device__ __forceinline__ uint32_t smem_u32(const void* p){
    return (uint32_t)__cvta_generic_to_shared(p);
}
__device__ __forceinline__ void cp16(uint32_t dst, const void* src, bool pred){
    int sz = pred ? 16 : 0;
    asm volatile("cp.async.cg.shared.global [%0],[%1],16,%2;\n"::"r"(dst),"l"(src),"r"(sz));
}
__device__ __forceinline__ void cp_commit(){ asm volatile("cp.async.commit_group;\n"::); }
template<int NW> __device__ __forceinline__ void cp_wait(){
    asm volatile("cp.async.wait_group %0;\n"::"n"(NW));
}
__device__ __forceinline__ void ldsm4(uint32_t &r0,uint32_t &r1,uint32_t &r2,uint32_t &r3, uint32_t addr){
    asm volatile("ldmatrix.sync.aligned.m8n8.x4.shared.b16 {%0,%1,%2,%3},[%4];\n"
                 :"=r"(r0),"=r"(r1),"=r"(r2),"=r"(r3):"r"(addr));
}
__device__ __forceinline__ void ldsm4t(uint32_t &r0,uint32_t &r1,uint32_t &r2,uint32_t &r3, uint32_t addr){
    asm volatile("ldmatrix.sync.aligned.m8n8.x4.trans.shared.b16 {%0,%1,%2,%3},[%4];\n"
                 :"=r"(r0),"=r"(r1),"=r"(r2),"=r"(r3):"r"(addr));
}
__device__ __forceinline__ void mma16816(float* c,
        uint32_t a0,uint32_t a1,uint32_t a2,uint32_t a3, uint32_t b0,uint32_t b1){
    asm volatile("mma.sync.aligned.m16n8k16.row.col.f32.bf16.bf16.f32 "
                 "{%0,%1,%2,%3},{%4,%5,%6,%7},{%8,%9},{%0,%1,%2,%3};\n"
                 :"+f"(c[0]),"+f"(c[1]),"+f"(c[2]),"+f"(c[3])
                 :"r"(a0),"r"(a1),"r"(a2),"r"(a3),"r"(b0),"r"(b1));
}
__device__ __forceinline__ void split2_store(float v0, float v1,
                                             __nv_bfloat16* hp, __nv_bfloat16* lp){
    __nv_bfloat162 h = __float22bfloat162_rn(make_float2(v0, v1));
    float2 hf = __bfloat1622float2(h);
    __nv_bfloat162 l = __float22bfloat162_rn(make_float2(v0 - hf.x, v1 - hf.y));
    *(__nv_bfloat162*)hp = h;
    *(__nv_bfloat162*)lp = l;
}

// ================= split: fp32 -> bf16 hi/lo planes =================
__global__ void split_kernel(const float* __restrict__ in, long long n, int which)
{
    __nv_bfloat16 *hp, *lp;
    switch (which){
        case 0: hp = g_xh;  lp = g_xl;  break;
        case 1: hp = g_wgh; lp = g_wgl; break;
        case 2: hp = g_wuh; lp = g_wul; break;
        case 3: hp = g_wdh; lp = g_wdl; break;
        case 4: hp = g_sgh; lp = g_sgl; break;
        case 5: hp = g_suh; lp = g_sul; break;
        default:hp = g_sdh; lp = g_sdl; break;
    }
    long long i = ((long long)blockIdx.x * blockDim.x + threadIdx.x) * 4;
    if (i < n){
        float4 v = *(const float4*)(in + i);
        __nv_bfloat162 h01 = __float22bfloat162_rn(make_float2(v.x, v.y));
        __nv_bfloat162 h23 = __float22bfloat162_rn(make_float2(v.z, v.w));
        float2 f01 = __bfloat1622float2(h01), f23 = __bfloat1622float2(h23);
        *(__nv_bfloat162*)(hp + i)     = h01;
        *(__nv_bfloat162*)(hp + i + 2) = h23;
        *(__nv_bfloat162*)(lp + i)     = __float22bfloat162_rn(make_float2(v.x - f01.x, v.y - f01.y));
        *(__nv_bfloat162*)(lp + i + 2) = __float22bfloat162_rn(make_float2(v.z - f23.x, v.w - f23.y));
    }
}

// ================= router: softmax + top-6 =================
__global__ void router_kernel(const float* __restrict__ x, const float* __restrict__ wg)
{
    const int t = blockIdx.x;
    const int tid = threadIdx.x;               // 128 threads
    const int warp = tid >> 5, lane = tid & 31;
    __shared__ float s_sc[N_EXP];
    const float* xr = x + (size_t)t * D_MODEL;
    for (int e = warp; e < N_EXP; e += 4){
        const float* w = wg + (size_t)e * D_MODEL;
        float acc = 0.f;
        for (int d = lane * 4; d < D_MODEL; d += 128){
            float4 xv = *(const float4*)(xr + d);
            float4 wv = *(const float4*)(w + d);
            acc += xv.x*wv.x + xv.y*wv.y + xv.z*wv.z + xv.w*wv.w;
        }
        #pragma unroll
        for (int o = 16; o; o >>= 1) acc += __shfl_xor_sync(0xffffffffu, acc, o);
        if (lane == 0) s_sc[e] = acc;
    }
    __syncthreads();
    if (warp == 0){
        float v = s_sc[lane];
        float m = v;
        #pragma unroll
        for (int o = 16; o; o >>= 1) m = fmaxf(m, __shfl_xor_sync(0xffffffffu, m, o));
        float ev = expf(v - m);
        float Z = ev;
        #pragma unroll
        for (int o = 16; o; o >>= 1) Z += __shfl_xor_sync(0xffffffffu, Z, o);
        float s = ev / Z;
        float cur = s, sum6 = 0.f;
        int sel_idx = 0; float sel_val = 0.f;
        #pragma unroll
        for (int k = 0; k < TOPK; k++){
            float bv = cur; int bi = lane;
            #pragma unroll
            for (int o = 16; o; o >>= 1){
                float ovv = __shfl_xor_sync(0xffffffffu, bv, o);
                int   oi  = __shfl_xor_sync(0xffffffffu, bi, o);
                if (ovv > bv || (ovv == bv && oi < bi)){ bv = ovv; bi = oi; }
            }
            sum6 += bv;
            if (lane == k){ sel_idx = bi; sel_val = bv; }
            if (lane == bi) cur = -1.f;
        }
        if (lane < TOPK){
            g_topk_idx[t*TOPK + lane] = sel_idx;
            g_topk_w [t*TOPK + lane] = sel_val / (sum6 + 1e-20f);
        }
    }
}

// ======= dispatch: flattened-order positions =======
__global__ void dispatch_kernel()
{
    __shared__ int s_idx[NASSIGN];
    for (int i = threadIdx.x; i < NASSIGN; i += 1024) s_idx[i] = g_topk_idx[i];
    __syncthreads();
    const int warp = threadIdx.x >> 5;   // expert id
    const int lane = threadIdx.x & 31;
    int count = 0;
    for (int base = 0; base < NASSIGN; base += 32){
        int eidx = s_idx[base + lane];
        unsigned msk = __ballot_sync(0xffffffffu, eidx == warp);
        if (eidx == warp){
            int p = count + __popc(msk & ((1u << lane) - 1u));
            g_pos[base + lane] = p;
            if (p < CAP) g_rows[warp*CAP + p] = base + lane;
        }
        count += __popc(msk);
    }
    if (lane == 0) g_count[warp] = (count < CAP) ? count : CAP;
}

// ======= fused gate/up SwiGLU grouped GEMM (BK=32, cp.async double-buffer) =======
template<bool GATHER>
__global__ __launch_bounds__(256, 2)
void gateup_kernel(int N, int Mtot)
{
    extern __shared__ __align__(16) char smem[];
    int* s_tok = (int*)(smem + 2*GU_BUFSZ);

    const int e = blockIdx.z;
    const int rows = GATHER ? g_count[e] : Mtot;
    const int m0 = blockIdx.y * BM;
    if (m0 >= rows) return;
    const int n0 = blockIdx.x * BN;
    const int tid = threadIdx.x;
    const int lane = tid & 31, warp = tid >> 5;
    const int wm = warp & 3, wn = warp >> 2;

    const __nv_bfloat16* wgh = GATHER ? g_wgh + (size_t)e*D_MODEL*N : g_sgh;
    const __nv_bfloat16* wgl = GATHER ? g_wgl + (size_t)e*D_MODEL*N : g_sgl;
    const __nv_bfloat16* wuh = GATHER ? g_wuh + (size_t)e*D_MODEL*N : g_suh;
    const __nv_bfloat16* wul = GATHER ? g_wul + (size_t)e*D_MODEL*N : g_sul;
    __nv_bfloat16* hh = GATHER ? g_Hh + (size_t)e*CAP*N : g_Hsh;
    __nv_bfloat16* hl = GATHER ? g_Hl + (size_t)e*CAP*N : g_Hsl;

    if (tid < BM){
        int r = m0 + tid;
        s_tok[tid] = (r < rows) ? (GATHER ? (g_rows[e*CAP + r] / TOPK) : r) : -1;
    }
    __syncthreads();

    const uint32_t sbase = smem_u32(smem);

    // ---- staging map ----
    const int arow = tid >> 1, ahalf = tid & 1;
    const bool apred = s_tok[arow] >= 0;
    const size_t abase = (size_t)(apred ? s_tok[arow] : 0) * D_MODEL + ahalf*16;
    const uint32_t aDst = sbase + (uint32_t)(arow*80 + ahalf*32);
    const int brow = tid >> 3, bch = (tid & 7) * 8;
    const size_t bsoff = (size_t)brow * N + n0 + bch;
    const uint32_t bDst = sbase + (uint32_t)(brow*144 + bch*2);

    auto stage = [&](int kt, int b){
        const uint32_t bo = (uint32_t)(b * GU_BUFSZ);
        const int k0 = kt * BK;
        cp16(bo + aDst + GU_AH,      g_xh + abase + k0,     apred);
        cp16(bo + aDst + GU_AH + 16, g_xh + abase + k0 + 8, apred);
        cp16(bo + aDst + GU_AL,      g_xl + abase + k0,     apred);
        cp16(bo + aDst + GU_AL + 16, g_xl + abase + k0 + 8, apred);
        const size_t ks = (size_t)k0 * N + bsoff;
        cp16(bo + bDst + GU_BGH, wgh + ks, true);
        cp16(bo + bDst + GU_BGL, wgl + ks, true);
        cp16(bo + bDst + GU_BUH, wuh + ks, true);
        cp16(bo + bDst + GU_BUL, wul + ks, true);
    };

    // ---- fragment bases (buffer 0) ----
    const int aRow = wm*32 + (lane & 15);
    const int aCol = 8 * (lane >> 4);
    const uint32_t aFH = sbase + GU_AH + (uint32_t)(aRow*80 + aCol*2);
    const uint32_t aFL = sbase + GU_AL + (uint32_t)(aRow*80 + aCol*2);
    const int bRow = lane & 15;
    const int bCol = wn*32 + 8*(lane >> 4);
    const uint32_t bF = sbase + (uint32_t)(bRow*144 + bCol*2);

    float accG[2][4][4] = {};
    float accU[2][4][4] = {};

    const int KT = D_MODEL / BK;
    stage(0, 0); cp_commit();
    for (int kt = 0; kt < KT; kt++){
        const int b = kt & 1;
        if (kt + 1 < KT){ stage(kt + 1, b ^ 1); cp_commit(); cp_wait<1>(); }
        else cp_wait<0>();
        __syncthreads();
        const uint32_t bo = (uint32_t)(b * GU_BUFSZ);
        #pragma unroll
        for (int ks = 0; ks < 2; ks++){
            uint32_t ah[2][4], al[2][4];
            #pragma unroll
            for (int mt = 0; mt < 2; mt++){
                const uint32_t o = bo + (uint32_t)(mt*16*80 + ks*32);
                ldsm4(ah[mt][0],ah[mt][1],ah[mt][2],ah[mt][3], aFH + o);
                ldsm4(al[mt][0],al[mt][1],al[mt][2],al[mt][3], aFL + o);
            }
            {   // gate
                uint32_t bh[8], bl[8];
                #pragma unroll
                for (int hf = 0; hf < 2; hf++){
                    const uint32_t o = bo + (uint32_t)(ks*16*144 + hf*32);
                    ldsm4t(bh[hf*4+0],bh[hf*4+1],bh[hf*4+2],bh[hf*4+3], bF + GU_BGH + o);
                    ldsm4t(bl[hf*4+0],bl[hf*4+1],bl[hf*4+2],bl[hf*4+3], bF + GU_BGL + o);
                }
                #pragma unroll
                for (int mt = 0; mt < 2; mt++)
                    #pragma unroll
                    for (int ns = 0; ns < 4; ns++){
                        const int bi = (ns>>1)*4 + (ns&1)*2;
                        mma16816(accG[mt][ns], ah[mt][0],ah[mt][1],ah[mt][2],ah[mt][3], bh[bi], bh[bi+1]);
                        mma16816(accG[mt][ns], ah[mt][0],ah[mt][1],ah[mt][2],ah[mt][3], bl[bi], bl[bi+1]);
                        mma16816(accG[mt][ns], al[mt][0],al[mt][1],al[mt][2],al[mt][3], bh[bi], bh[bi+1]);
                    }
            }
            {   // up
                uint32_t bh[8], bl[8];
                #pragma unroll
                for (int hf = 0; hf < 2; hf++){
                    const uint32_t o = bo + (uint32_t)(ks*16*144 + hf*32);
                    ldsm4t(bh[hf*4+0],bh[hf*4+1],bh[hf*4+2],bh[hf*4+3], bF + GU_BUH + o);
                    ldsm4t(bl[hf*4+0],bl[hf*4+1],bl[hf*4+2],bl[hf*4+3], bF + GU_BUL + o);
                }
                #pragma unroll
                for (int mt = 0; mt < 2; mt++)
                    #pragma unroll
                    for (int ns = 0; ns < 4; ns++){
                        const int bi = (ns>>1)*4 + (ns&1)*2;
                        mma16816(accU[mt][ns], ah[mt][0],ah[mt][1],ah[mt][2],ah[mt][3], bh[bi], bh[bi+1]);
                        mma16816(accU[mt][ns], ah[mt][0],ah[mt][1],ah[mt][2],ah[mt][3], bl[bi], bl[bi+1]);
                        mma16816(accU[mt][ns], al[mt][0],al[mt][1],al[mt][2],al[mt][3], bh[bi], bh[bi+1]);
                    }
            }
        }
        __syncthreads();
    }

    // ---- epilogue: h = silu(g)*u, stored as split planes ----
    const int gid = lane >> 2, tg = lane & 3;
    #pragma unroll
    for (int mt = 0; mt < 2; mt++){
        #pragma unroll
        for (int hf = 0; hf < 2; hf++){
            const int r = m0 + wm*32 + mt*16 + gid + hf*8;
            if (r < rows){
                #pragma unroll
                for (int ns = 0; ns < 4; ns++){
                    float g0 = accG[mt][ns][hf*2+0], g1 = accG[mt][ns][hf*2+1];
                    float u0 = accU[mt][ns][hf*2+0], u1 = accU[mt][ns][hf*2+1];
                    float h0 = g0 / (1.f + expf(-g0)) * u0;
                    float h1 = g1 / (1.f + expf(-g1)) * u1;
                    const int c = n0 + wn*32 + ns*8 + tg*2;
                    const size_t idx = (size_t)r * N + c;
                    split2_store(h0, h1, hh + idx, hl + idx);
                }
            }
        }
    }
}

// ======= down grouped GEMM (BK=32) — GATHER variant fuses weighted combine =======
template<bool GATHER>
__global__ __launch_bounds__(256, 2)
void down_kernel(float* __restrict__ outp, int K, int Mtot)
{
    extern __shared__ __align__(16) char smem[];
    int*   s_tok = (int*)  (smem + 2*DN_BUFSZ);
    float* s_w   = (float*)(smem + 2*DN_BUFSZ + 512);

    const int e = blockIdx.z;
    const int rows = GATHER ? g_count[e] : Mtot;
    const int m0 = blockIdx.y * BM;
    if (m0 >= rows) return;
    const int n0 = blockIdx.x * BN;
    const int tid = threadIdx.x;
    const int lane = tid & 31, warp = tid >> 5;
    const int wm = warp & 3, wn = warp >> 2;

    const __nv_bfloat16* Ahp = GATHER ? g_Hh + (size_t)e*CAP*K : g_Hsh;
    const __nv_bfloat16* Alp = GATHER ? g_Hl + (size_t)e*CAP*K : g_Hsl;
    const __nv_bfloat16* Bhp = GATHER ? g_wdh + (size_t)e*(size_t)K*D_MODEL : g_sdh;
    const __nv_bfloat16* Blp = GATHER ? g_wdl + (size_t)e*(size_t)K*D_MODEL : g_sdl;

    if (tid < BM){
        int r = m0 + tid;
        if (r < rows){
            if (GATHER){
                int a = g_rows[e*CAP + r];
                s_tok[tid] = a / TOPK;
                s_w[tid] = g_topk_w[a];
            } else {
                s_tok[tid] = r;
                s_w[tid] = 1.f;
            }
        } else s_tok[tid] = -1;
    }
    __syncthreads();

    const uint32_t sbase = smem_u32(smem);
    const int arow = tid >> 1, ahalf = tid & 1;
    const bool apred = (m0 + arow) < rows;
    const size_t abase = (size_t)(apred ? (m0 + arow) : 0) * K + ahalf*16;
    const uint32_t aDst = sbase + (uint32_t)(arow*80 + ahalf*32);
    const int brow = tid >> 3, bch = (tid & 7) * 8;
    const size_t bsoff = (size_t)brow * D_MODEL + n0 + bch;
    const uint32_t bDst = sbase + (uint32_t)(brow*144 + bch*2);

    auto stage = [&](int kt, int b){
        const uint32_t bo = (uint32_t)(b * DN_BUFSZ);
        const int k0 = kt * BK;
        cp16(bo + aDst + DN_AH,      Ahp + abase + k0,     apred);
        cp16(bo + aDst + DN_AH + 16, Ahp + abase + k0 + 8, apred);
        cp16(bo + aDst + DN_AL,      Alp + abase + k0,     apred);
        cp16(bo + aDst + DN_AL + 16, Alp + abase + k0 + 8, apred);
        const size_t ks = (size_t)k0 * D_MODEL + bsoff;
        cp16(bo + bDst + DN_BH, Bhp + ks, true);
        cp16(bo + bDst + DN_BL, Blp + ks, true);
    };

    const int aRow = wm*32 + (lane & 15);
    const int aCol = 8 * (lane >> 4);
    const uint32_t aFH = sbase + DN_AH + (uint32_t)(aRow*80 + aCol*2);
    const uint32_t aFL = sbase + DN_AL + (uint32_t)(aRow*80 + aCol*2);
    const int bRow = lane & 15;
    const int bCol = wn*32 + 8*(lane >> 4);
    const uint32_t bF = sbase + (uint32_t)(bRow*144 + bCol*2);

    float acc[2][4][4] = {};

    const int KT = K / BK;
    stage(0, 0); cp_commit();
    for (int kt = 0; kt < KT; kt++){
        const int b = kt & 1;
        if (kt + 1 < KT){ stage(kt + 1, b ^ 1); cp_commit(); cp_wait<1>(); }
        else cp_wait<0>();
        __syncthreads();
        const uint32_t bo = (uint32_t)(b * DN_BUFSZ);
        #pragma unroll
        for (int ks = 0; ks < 2; ks++){
            uint32_t ah[2][4], al[2][4];
            #pragma unroll
            for (int mt = 0; mt < 2; mt++){
                const uint32_t o = bo + (uint32_t)(mt*16*80 + ks*32);
                ldsm4(ah[mt][0],ah[mt][1],ah[mt][2],ah[mt][3], aFH + o);
                ldsm4(al[mt][0],al[mt][1],al[mt][2],al[mt][3], aFL + o);
            }
            uint32_t bh[8], bl[8];
            #pragma unroll
            for (int hf = 0; hf < 2; hf++){
                const uint32_t o = bo + (uint32_t)(ks*16*144 + hf*32);
                ldsm4t(bh[hf*4+0],bh[hf*4+1],bh[hf*4+2],bh[hf*4+3], bF + DN_BH + o);
                ldsm4t(bl[hf*4+0],bl[hf*4+1],bl[hf*4+2],bl[hf*4+3], bF + DN_BL + o);
            }
            #pragma unroll
            for (int mt = 0; mt < 2; mt++)
                #pragma unroll
                for (int ns = 0; ns < 4; ns++){
                    const int bi = (ns>>1)*4 + (ns&1)*2;
                    mma16816(acc[mt][ns], ah[mt][0],ah[mt][1],ah[mt][2],ah[mt][3], bh[bi], bh[bi+1]);
                    mma16816(acc[mt][ns], ah[mt][0],ah[mt][1],ah[mt][2],ah[mt][3], bl[bi], bl[bi+1]);
                    mma16816(acc[mt][ns], al[mt][0],al[mt][1],al[mt][2],al[mt][3], bh[bi], bh[bi+1]);
                }
        }
        __syncthreads();
    }

    // epilogue
    const int gid = lane >> 2, tg = lane & 3;
    #pragma unroll
    for (int mt = 0; mt < 2; mt++){
        #pragma unroll
        for (int hf = 0; hf < 2; hf++){
            const int rl = wm*32 + mt*16 + gid + hf*8;
            const int tok = s_tok[rl];
            if (tok >= 0){
                #pragma unroll
                for (int ns = 0; ns < 4; ns++){
                    const int c = n0 + wn*32 + ns*8 + tg*2;
                    float* op = outp + (size_t)tok * D_MODEL + c;
                    if (GATHER){
                        const float w = s_w[rl];
                        atomicAdd(op,     w * acc[mt][ns][hf*2+0]);
                        atomicAdd(op + 1, w * acc[mt][ns][hf*2+1]);
                    } else {
                        *(float2*)op = make_float2(acc[mt][ns][hf*2+0], acc[mt][ns][hf*2+1]);
                    }
                }
            }
        }
    }
}

// ---------------- launcher ----------------
static inline int split_grid(long long n){ return (int)((n/4 + 255) / 256); }

extern "C" void kernel_launch(void* const* d_in, const int* in_sizes, int n_in,
                              void* d_out, int out_size)
{
    (void)in_sizes; (void)n_in; (void)out_size;
    const float* x   = (const float*)d_in[0];
    const float* wgr = (const float*)d_in[1];
    const float* wg  = (const float*)d_in[2];
    const float* wu  = (const float*)d_in[3];
    const float* wd  = (const float*)d_in[4];
    const float* wsg = (const float*)d_in[5];
    const float* wsu = (const float*)d_in[6];
    const float* wsd = (const float*)d_in[7];
    float* out = (float*)d_out;

    cudaFuncSetAttribute(gateup_kernel<true >, cudaFuncAttributeMaxDynamicSharedMemorySize, GU_SMEM);
    cudaFuncSetAttribute(gateup_kernel<false>, cudaFuncAttributeMaxDynamicSharedMemorySize, GU_SMEM);
    cudaFuncSetAttribute(down_kernel<true >,   cudaFuncAttributeMaxDynamicSharedMemorySize, DN_SMEM);
    cudaFuncSetAttribute(down_kernel<false>,   cudaFuncAttributeMaxDynamicSharedMemorySize, DN_SMEM);

    const long long nX = (long long)T_TOKENS * D_MODEL;
    const long long nW = (long long)N_EXP * D_MODEL * F_INTER;
    const long long nS = (long long)D_MODEL * FS_INTER;

    split_kernel<<<split_grid(nX), 256>>>(x,   nX, 0);
    split_kernel<<<split_grid(nW), 256>>>(wg,  nW, 1);
    split_kernel<<<split_grid(nW), 256>>>(wu,  nW, 2);
    split_kernel<<<split_grid(nW), 256>>>(wd,  nW, 3);
    split_kernel<<<split_grid(nS), 256>>>(wsg, nS, 4);
    split_kernel<<<split_grid(nS), 256>>>(wsu, nS, 5);
    split_kernel<<<split_grid(nS), 256>>>(wsd, nS, 6);

    router_kernel<<<T_TOKENS, 128>>>(x, wgr);
    dispatch_kernel<<<1, 1024>>>();

    // expert gate/up SwiGLU -> H planes
    gateup_kernel<true ><<<dim3(F_INTER/BN,  CAP/BM,      N_EXP), 256, GU_SMEM>>>(F_INTER,  0);
    // shared-expert gate/up -> Hs planes
    gateup_kernel<false><<<dim3(FS_INTER/BN, T_TOKENS/BM, 1    ), 256, GU_SMEM>>>(FS_INTER, T_TOKENS);
    // shared down writes out FIRST (plain stores cover all of out)...
    down_kernel<false><<<dim3(D_MODEL/BN, T_TOKENS/BM, 1    ), 256, DN_SMEM>>>(out, FS_INTER, T_TOKENS);
    // ...then expert down accumulates weighted contributions atomically
    down_kernel<true ><<<dim3(D_MODEL/BN, CAP/BM,      N_EXP), 256, DN_SMEM>>>(out, F_INTER,  0);
}